// round 6
// baseline (speedup 1.0000x reference)
#include <cuda_runtime.h>
#include <cuda_bf16.h>

// DynamicPatchAggregator — gather, float4 along w, branchless 2x2x2 body with
// EXPLICIT 8-wide load batching per channel (float4 v[8] staging) and an
// 84-register budget so the loads stay in flight (register-capped MLP fix).
// vol=192^3, patch=96^3, stride=48 -> starts {0,48,96}, 27 patches, C=2.
// Coverage complete -> upsampled global branch contributes 0; skipped.

#define VOL 192
#define PATCH 96
#define STRIDE 48
#define CH_STRIDE (PATCH*PATCH*PATCH)          // 884736
#define PATCH_STRIDE (2*CH_STRIDE)             // per-k stride (C=2)
#define OUT_CH_STRIDE (VOL*VOL*VOL)            // 7077888

__device__ __forceinline__ float gweight(int l) {
    float t = (float)(l - 48) * (1.0f / 12.0f);
    return __expf(-0.5f * t * t);
}

// Branchless per-axis info: two (offset, weight) slots; slot1 duplicates
// slot0 (weight 0) when only one patch covers x.
__device__ __forceinline__ void axis2(int x, int simul, int locmul,
                                      int* off0, int* off1,
                                      float* g0, float* g1) {
    int lo = (x - 48) / 48; lo = max(lo, 0);
    int hi = min(x / 48, 2);
    int has2 = hi - lo;
    int l0 = x - lo * STRIDE;
    int l1 = l0 - has2 * STRIDE;
    *off0 = lo * simul + l0 * locmul;
    *off1 = (lo + has2) * simul + l1 * locmul;
    *g0 = gweight(l0);
    *g1 = has2 ? gweight(l1) : 0.f;
}

__global__ __launch_bounds__(192, 4) void agg_kernel_b8(const float* __restrict__ patch,
                                                        float* __restrict__ out) {
    const int w0 = threadIdx.x * 4;              // 0,4,...,188
    const int h  = blockIdx.x * 4 + threadIdx.y; // 0..191
    const int d  = blockIdx.y;                   // 0..191

    int offD0, offD1, offH0, offH1;
    float gd0, gd1, gh0, gh1;
    axis2(d, 9 * PATCH_STRIDE, PATCH * PATCH, &offD0, &offD1, &gd0, &gd1);
    axis2(h, 3 * PATCH_STRIDE, PATCH,         &offH0, &offH1, &gh0, &gh1);

    // w axis: 4-wide group shares one covering set (boundaries 48-aligned).
    int wlo = (w0 - 48) / 48; wlo = max(wlo, 0);
    int whi = min(w0 / 48, 2);
    int whas2 = whi - wlo;
    int wl0 = w0 - wlo * STRIDE;
    int wl1 = wl0 - whas2 * STRIDE;
    const int offW0 = wlo * PATCH_STRIDE + wl0;
    const int offW1 = (wlo + whas2) * PATCH_STRIDE + wl1;

    float gw0[4], gw1[4];
    #pragma unroll
    for (int j = 0; j < 4; j++) {
        gw0[j] = gweight(wl0 + j);
        gw1[j] = whas2 ? gweight(wl1 + j) : 0.f;
    }

    // 8 combo offsets (32-bit) — slot order: (d0h0w0, d0h0w1, d0h1w0, ...,
    // d1h1w1). Duplicated slots are L1/L2 hits (zero extra DRAM).
    int qoff[8];
    qoff[0] = offD0 + offH0 + offW0;
    qoff[1] = offD0 + offH0 + offW1;
    qoff[2] = offD0 + offH1 + offW0;
    qoff[3] = offD0 + offH1 + offW1;
    qoff[4] = offD1 + offH0 + offW0;
    qoff[5] = offD1 + offH0 + offW1;
    qoff[6] = offD1 + offH1 + offW0;
    qoff[7] = offD1 + offH1 + offW1;

    const float wdh[4] = { gd0 * gh0, gd0 * gh1, gd1 * gh0, gd1 * gh1 };

    float4 acc0 = make_float4(0.f, 0.f, 0.f, 0.f);
    float4 acc1 = make_float4(0.f, 0.f, 0.f, 0.f);
    float4 v[8];

    // ---- channel 0: 8 back-to-back LDG.128, then FMAs ----
    #pragma unroll
    for (int j = 0; j < 8; j++)
        v[j] = __ldcs(reinterpret_cast<const float4*>(patch + qoff[j]));
    #pragma unroll
    for (int j = 0; j < 8; j++) {
        const float* gwv = (j & 1) ? gw1 : gw0;
        const float s = wdh[j >> 1];
        acc0.x = fmaf(s * gwv[0], v[j].x, acc0.x);
        acc0.y = fmaf(s * gwv[1], v[j].y, acc0.y);
        acc0.z = fmaf(s * gwv[2], v[j].z, acc0.z);
        acc0.w = fmaf(s * gwv[3], v[j].w, acc0.w);
    }

    // ---- channel 1: reuse staging array ----
    #pragma unroll
    for (int j = 0; j < 8; j++)
        v[j] = __ldcs(reinterpret_cast<const float4*>(patch + CH_STRIDE + qoff[j]));
    #pragma unroll
    for (int j = 0; j < 8; j++) {
        const float* gwv = (j & 1) ? gw1 : gw0;
        const float s = wdh[j >> 1];
        acc1.x = fmaf(s * gwv[0], v[j].x, acc1.x);
        acc1.y = fmaf(s * gwv[1], v[j].y, acc1.y);
        acc1.z = fmaf(s * gwv[2], v[j].z, acc1.z);
        acc1.w = fmaf(s * gwv[3], v[j].w, acc1.w);
    }

    const float gdsh = (gd0 + gd1) * (gh0 + gh1);
    float4 inv;
    inv.x = __frcp_rn(fmaf(gdsh, gw0[0] + gw1[0], 1e-20f));
    inv.y = __frcp_rn(fmaf(gdsh, gw0[1] + gw1[1], 1e-20f));
    inv.z = __frcp_rn(fmaf(gdsh, gw0[2] + gw1[2], 1e-20f));
    inv.w = __frcp_rn(fmaf(gdsh, gw0[3] + gw1[3], 1e-20f));

    acc0.x *= inv.x; acc0.y *= inv.y; acc0.z *= inv.z; acc0.w *= inv.w;
    acc1.x *= inv.x; acc1.y *= inv.y; acc1.z *= inv.z; acc1.w *= inv.w;

    const int vidx = (d * VOL + h) * VOL + w0;
    __stcs(reinterpret_cast<float4*>(out + vidx), acc0);
    __stcs(reinterpret_cast<float4*>(out + vidx + OUT_CH_STRIDE), acc1);
}

extern "C" void kernel_launch(void* const* d_in, const int* in_sizes, int n_in,
                              void* d_out, int out_size) {
    const float* patch = (const float*)d_in[0];
    float* out = (float*)d_out;
    dim3 block(48, 4, 1);   // 48 float4-groups x 4 h-rows = 192 threads
    dim3 grid(VOL / 4, VOL, 1);
    agg_kernel_b8<<<grid, block>>>(patch, out);
}

// round 9
// speedup vs baseline: 1.1865x; 1.1865x over previous
#include <cuda_runtime.h>
#include <cuda_bf16.h>

// DynamicPatchAggregator — gather, float4 along w, REGION-SPECIALIZED paths.
// d/h axes split into coverage classes: [0,48)u[144,192) -> 1 covering patch,
// [48,144) -> 2. All four (nd,nh) region classes are exactly 96x96 in d x h,
// selected by blockIdx.z -> every block runs one fully-specialized
// straight-line path (no divergence, no dead loads along d/h).
// w-axis keeps branchless slot-dup (same-address load = L1 hit).
// vol=192^3, patch=96^3, stride=48 -> starts {0,48,96}, 27 patches, C=2.
// Coverage complete -> upsampled global branch contributes 0; skipped.

#define VOL 192
#define PATCH 96
#define STRIDE 48
#define CH_STRIDE (PATCH*PATCH*PATCH)          // 884736
#define PATCH_STRIDE (2*CH_STRIDE)             // per-k stride (C=2)
#define OUT_CH_STRIDE (VOL*VOL*VOL)            // 7077888

__device__ __forceinline__ float gweight(int l) {
    float t = (float)(l - 48) * (1.0f / 12.0f);
    return __expf(-0.5f * t * t);
}

template<int ND, int NH>
__device__ __forceinline__ void region_body(const float* __restrict__ patch,
                                            float* __restrict__ out,
                                            int d, int h, int w0) {
    // d axis (ND covering patches, compile-time)
    const int lod = max((d - 48) / 48, 0);
    const int ld0 = d - lod * STRIDE;
    float gd[2];
    int   offD[2];
    gd[0]  = gweight(ld0);
    offD[0] = lod * (9 * PATCH_STRIDE) + ld0 * (PATCH * PATCH);
    if (ND == 2) {
        gd[1]  = gweight(ld0 - STRIDE);
        offD[1] = offD[0] + 9 * PATCH_STRIDE - STRIDE * (PATCH * PATCH);
    }

    // h axis
    const int loh = max((h - 48) / 48, 0);
    const int lh0 = h - loh * STRIDE;
    float gh[2];
    int   offH[2];
    gh[0]  = gweight(lh0);
    offH[0] = loh * (3 * PATCH_STRIDE) + lh0 * PATCH;
    if (NH == 2) {
        gh[1]  = gweight(lh0 - STRIDE);
        offH[1] = offH[0] + 3 * PATCH_STRIDE - STRIDE * PATCH;
    }

    // w axis: branchless, slot1 duplicates slot0 (weight 0) when nw == 1.
    int wlo = max((w0 - 48) / 48, 0);
    int whi = min(w0 / 48, 2);
    const int whas2 = whi - wlo;
    const int wl0 = w0 - wlo * STRIDE;
    const int wl1 = wl0 - whas2 * STRIDE;
    const int offW0 = wlo * PATCH_STRIDE + wl0;
    const int offW1 = (wlo + whas2) * PATCH_STRIDE + wl1;

    float gw0[4], gw1[4];
    #pragma unroll
    for (int j = 0; j < 4; j++) {
        gw0[j] = gweight(wl0 + j);
        gw1[j] = whas2 ? gweight(wl1 + j) : 0.f;
    }

    float4 acc0 = make_float4(0.f, 0.f, 0.f, 0.f);
    float4 acc1 = make_float4(0.f, 0.f, 0.f, 0.f);

    #pragma unroll
    for (int id = 0; id < ND; id++) {
        #pragma unroll
        for (int ih = 0; ih < NH; ih++) {
            const float gdh = gd[id] * gh[ih];
            const int offDH = offD[id] + offH[ih];
            #pragma unroll
            for (int iw = 0; iw < 2; iw++) {
                const float* q = patch + offDH + (iw ? offW1 : offW0);
                const float* gwv = iw ? gw1 : gw0;
                const float4 v0 = __ldcs(reinterpret_cast<const float4*>(q));
                const float4 v1 = __ldcs(reinterpret_cast<const float4*>(q + CH_STRIDE));
                acc0.x = fmaf(gdh * gwv[0], v0.x, acc0.x);
                acc0.y = fmaf(gdh * gwv[1], v0.y, acc0.y);
                acc0.z = fmaf(gdh * gwv[2], v0.z, acc0.z);
                acc0.w = fmaf(gdh * gwv[3], v0.w, acc0.w);
                acc1.x = fmaf(gdh * gwv[0], v1.x, acc1.x);
                acc1.y = fmaf(gdh * gwv[1], v1.y, acc1.y);
                acc1.z = fmaf(gdh * gwv[2], v1.z, acc1.z);
                acc1.w = fmaf(gdh * gwv[3], v1.w, acc1.w);
            }
        }
    }

    const float gdsum = (ND == 2) ? gd[0] + gd[1] : gd[0];
    const float ghsum = (NH == 2) ? gh[0] + gh[1] : gh[0];
    const float gdsh = gdsum * ghsum;
    float4 inv;
    inv.x = __frcp_rn(fmaf(gdsh, gw0[0] + gw1[0], 1e-20f));
    inv.y = __frcp_rn(fmaf(gdsh, gw0[1] + gw1[1], 1e-20f));
    inv.z = __frcp_rn(fmaf(gdsh, gw0[2] + gw1[2], 1e-20f));
    inv.w = __frcp_rn(fmaf(gdsh, gw0[3] + gw1[3], 1e-20f));

    acc0.x *= inv.x; acc0.y *= inv.y; acc0.z *= inv.z; acc0.w *= inv.w;
    acc1.x *= inv.x; acc1.y *= inv.y; acc1.z *= inv.z; acc1.w *= inv.w;

    const int vidx = (d * VOL + h) * VOL + w0;
    __stcs(reinterpret_cast<float4*>(out + vidx), acc0);
    __stcs(reinterpret_cast<float4*>(out + vidx + OUT_CH_STRIDE), acc1);
}

__global__ __launch_bounds__(192, 6) void agg_kernel_reg(const float* __restrict__ patch,
                                                         float* __restrict__ out) {
    const int w0 = threadIdx.x * 4;                 // 0..188
    const int hr = blockIdx.x * 4 + threadIdx.y;    // 0..95 (region-local h)
    const int dr = blockIdx.y;                      // 0..95 (region-local d)
    const int hs = (hr < 48) ? hr : hr + 96;        // split-axis mapping
    const int ds = (dr < 48) ? dr : dr + 96;

    switch (blockIdx.z) {
        case 0: region_body<1, 1>(patch, out, ds,      hs,      w0); break;
        case 1: region_body<1, 2>(patch, out, ds,      hr + 48, w0); break;
        case 2: region_body<2, 1>(patch, out, dr + 48, hs,      w0); break;
        default: region_body<2, 2>(patch, out, dr + 48, hr + 48, w0); break;
    }
}

extern "C" void kernel_launch(void* const* d_in, const int* in_sizes, int n_in,
                              void* d_out, int out_size) {
    const float* patch = (const float*)d_in[0];
    float* out = (float*)d_out;
    dim3 block(48, 4, 1);       // 48 float4-groups x 4 region-h rows
    dim3 grid(24, 96, 4);       // 24 h-blocks x 96 d x 4 region classes
    agg_kernel_reg<<<grid, block>>>(patch, out);
}